// round 8
// baseline (speedup 1.0000x reference)
#include <cuda_runtime.h>
#include <cuda_bf16.h>

// Depthwise cross-correlation (VALID):
//   z_f: [128, 256, 7, 7]   (kernel, d_in[0])
//   x_f: [128, 256, 31, 31] (search, d_in[1])
//   out: [128, 256, 25, 25] fp32
//
// One CTA per (b,c) map, 192 threads. x tile staged in smem with padded row
// stride 36 (16B-aligned, zero pad). Each thread computes 4 adjacent output
// columns of one row using packed fp32x2 FMA (fma.rn.f32x2):
//   - x sliding-window pairs are all even-aligned -> direct b64 smem loads
//   - kernel row staged in two phase-shifted zero-padded layouts (zev/zod)
//     so both even and odd output columns consume the same x pairs.
// Per ky: 3 x loads (2x LDS.128 + LDS.64) + 4 z LDS.128 + 16 FMA2 = 32 lane-FMAs.

#define HX 31
#define WX 31
#define HZ 7
#define WZ 7
#define HO 25
#define WO 25
#define XS_STRIDE 36
#define NTHREADS 192
#define NTASKS (HO * 7)           // 25 rows * 7 groups of 4 cols = 175
#define XS_ELEMS (HX * XS_STRIDE) // 1116

typedef unsigned long long u64;

__device__ __forceinline__ u64 fma2(u64 a, u64 b, u64 c) {
    u64 d;
    asm("fma.rn.f32x2 %0, %1, %2, %3;" : "=l"(d) : "l"(a), "l"(b), "l"(c));
    return d;
}

__device__ __forceinline__ float hsum2(u64 p) {
    float lo, hi;
    asm("mov.b64 {%0, %1}, %2;" : "=f"(lo), "=f"(hi) : "l"(p));
    return lo + hi;
}

__global__ void __launch_bounds__(NTHREADS)
dwxcorr_kernel(const float* __restrict__ z, const float* __restrict__ x,
               float* __restrict__ out)
{
    __shared__ __align__(16) float xs[XS_ELEMS];  // 31*36 = 1116 floats
    __shared__ __align__(16) float zev[HZ][8];    // [z0..z6, 0]
    __shared__ __align__(16) float zod[HZ][8];    // [0, z0..z6]

    const int map = blockIdx.x;
    const int tid = threadIdx.x;

    const float* __restrict__ xg = x + (long long)map * (HX * WX);
    const float* __restrict__ zg = z + (long long)map * (HZ * WZ);

    // Stage kernel in both phase-shifted layouts
    if (tid < HZ * WZ) {
        int ky = tid / WZ;
        int kx = tid - ky * WZ;
        float v = zg[tid];
        zev[ky][kx]     = v;
        zod[ky][kx + 1] = v;
    }
    if (tid < HZ) {
        zev[tid][7] = 0.0f;
        zod[tid][0] = 0.0f;
    }

    // Stage search tile (fixed 6-trip unroll: 6*192 = 1152 >= 1116).
    // Increment-carried (r,c) avoids per-iteration division; LDGs front-batch.
    {
        int r = tid / XS_STRIDE;
        int c = tid - r * XS_STRIDE;
        #pragma unroll
        for (int k = 0; k < 6; ++k) {
            int i = tid + k * NTHREADS;
            if (i < XS_ELEMS)
                xs[i] = (c < WX) ? __ldg(&xg[r * WX + c]) : 0.0f;
            // advance by NTHREADS = 5*36 + 12
            r += 5;
            c += 12;
            if (c >= XS_STRIDE) { c -= XS_STRIDE; r += 1; }
        }
    }
    __syncthreads();

    if (tid >= NTASKS) return;

    const int oy = tid / 7;        // output row 0..24
    const int g  = tid - oy * 7;   // column group 0..6
    const int c0 = g * 4;          // first output column (multiple of 4)

    u64 acc0 = 0ull, acc1 = 0ull, acc2 = 0ull, acc3 = 0ull;

    #pragma unroll
    for (int ky = 0; ky < HZ; ++ky) {
        // 5 even-aligned x pairs covering x[c0 .. c0+9]; base is 16B-aligned.
        const u64* xw = (const u64*)&xs[(oy + ky) * XS_STRIDE + c0];
        ulonglong2 xa = ((const ulonglong2*)xw)[0];
        ulonglong2 xb = ((const ulonglong2*)xw)[1];
        u64 xp0 = xa.x, xp1 = xa.y, xp2 = xb.x, xp3 = xb.y, xp4 = xw[4];

        const ulonglong2* ze = (const ulonglong2*)zev[ky];
        const ulonglong2* zo = (const ulonglong2*)zod[ky];
        ulonglong2 ze01 = ze[0], ze23 = ze[1];
        ulonglong2 zo01 = zo[0], zo23 = zo[1];

        // col c0   (even): zev pairs vs xp[0..3]
        // col c0+1 (odd) : zod pairs vs xp[0..3]
        // col c0+2 (even): zev pairs vs xp[1..4]
        // col c0+3 (odd) : zod pairs vs xp[1..4]
        acc0 = fma2(ze01.x, xp0, acc0);
        acc1 = fma2(zo01.x, xp0, acc1);
        acc2 = fma2(ze01.x, xp1, acc2);
        acc3 = fma2(zo01.x, xp1, acc3);

        acc0 = fma2(ze01.y, xp1, acc0);
        acc1 = fma2(zo01.y, xp1, acc1);
        acc2 = fma2(ze01.y, xp2, acc2);
        acc3 = fma2(zo01.y, xp2, acc3);

        acc0 = fma2(ze23.x, xp2, acc0);
        acc1 = fma2(zo23.x, xp2, acc1);
        acc2 = fma2(ze23.x, xp3, acc2);
        acc3 = fma2(zo23.x, xp3, acc3);

        acc0 = fma2(ze23.y, xp3, acc0);
        acc1 = fma2(zo23.y, xp3, acc1);
        acc2 = fma2(ze23.y, xp4, acc2);
        acc3 = fma2(zo23.y, xp4, acc3);
    }

    float* __restrict__ og = out + (long long)map * (HO * WO) + oy * WO + c0;
    og[0] = hsum2(acc0);
    if (c0 + 1 < WO) og[1] = hsum2(acc1);
    if (c0 + 2 < WO) og[2] = hsum2(acc2);
    if (c0 + 3 < WO) og[3] = hsum2(acc3);
}

extern "C" void kernel_launch(void* const* d_in, const int* in_sizes, int n_in,
                              void* d_out, int out_size)
{
    const float* z = (const float*)d_in[0];   // z_f [128,256,7,7]
    const float* x = (const float*)d_in[1];   // x_f [128,256,31,31]
    float* out = (float*)d_out;               // [128,256,25,25]

    dwxcorr_kernel<<<128 * 256, NTHREADS>>>(z, x, out);
}